// round 4
// baseline (speedup 1.0000x reference)
#include <cuda_runtime.h>
#include <cstdint>

// ---------------------------------------------------------------------------
// FullSelfAttention (content + positional attention blend), fp32 baseline.
//   B=2, S=2048, D=768, H=12, DH=64, gamma=0.5, scale=1/8
// Outputs (concatenated in d_out):
//   [0)            attn_out  [B,S,D]      = 3,145,728 floats
//   [3145728)      attn_prob [B,S,S,H]    = 100,663,296 floats
// ---------------------------------------------------------------------------

static constexpr int B = 2, S = 2048, D = 768, H = 12, DH = 64;
static constexpr int N_TOK = B * S;     // 4096
static constexpr int G_I = B * H;       // 24 batched heads (content stream)
static constexpr int G_P = H;           // 12 batched heads (positional stream)
static constexpr float SCALE_SM = 0.125f;   // 1/sqrt(64) * smoothing(1.0)

static constexpr size_t OUT_ATTN = (size_t)B * S * D;       // 3145728

// --------------------------- scratch (device globals) -----------------------
__device__ float g_Wp[5 * D * D];                       // permuted weights
__device__ float g_QI[(size_t)G_I * S * DH];            // [b,h,i,d]
__device__ float g_KI[(size_t)G_I * S * DH];
__device__ float g_V [(size_t)G_I * S * DH];
__device__ float g_QP[(size_t)G_P * S * DH];            // [h,i,d]
__device__ float g_KP[(size_t)G_P * S * DH];
__device__ float g_SI[(size_t)G_I * S * S];             // content scores/probs
__device__ float g_SP[(size_t)G_P * S * S];             // positional scores/probs
__device__ float g_AO[(size_t)N_TOK * D];               // attn_out pre-projection

// 16 FMAs of a 4x4 microtile
#define FMA16(acc, a, b)                                                          \
    acc[0][0] += a.x*b.x; acc[0][1] += a.x*b.y; acc[0][2] += a.x*b.z; acc[0][3] += a.x*b.w; \
    acc[1][0] += a.y*b.x; acc[1][1] += a.y*b.y; acc[1][2] += a.y*b.z; acc[1][3] += a.y*b.w; \
    acc[2][0] += a.z*b.x; acc[2][1] += a.z*b.y; acc[2][2] += a.z*b.z; acc[2][3] += a.z*b.w; \
    acc[3][0] += a.w*b.x; acc[3][1] += a.w*b.y; acc[3][2] += a.w*b.z; acc[3][3] += a.w*b.w;

// ---------------------------------------------------------------------------
// Weight permutation: reference reshapes proj to [..., DH, H], so head h uses
// source columns d*H + h. Build Wp[:,h*64+d] head-contiguous.
// blockIdx.z selects which of the 5 weights; all 5 done in one launch.
// ---------------------------------------------------------------------------
__global__ void __launch_bounds__(256) k_permW(const float* __restrict__ W0,
                                               const float* __restrict__ W1,
                                               const float* __restrict__ W2,
                                               const float* __restrict__ W3,
                                               const float* __restrict__ W4) {
    int idx = blockIdx.x * 256 + threadIdx.x;
    if (idx >= D * D) return;
    int w = blockIdx.z;
    const float* Wsrc = (w == 0) ? W0 : (w == 1) ? W1 : (w == 2) ? W2
                       : (w == 3) ? W3 : W4;
    int k = idx / D, n = idx % D;
    int h = n / DH, d = n % DH;
    g_Wp[(size_t)w * D * D + idx] = Wsrc[k * D + d * H + h];
}

// ---------------------------------------------------------------------------
// Projection GEMM: C = A[M,768] @ Wp[widx][768,768], output scattered to
// per-head layout dst[((b*H+h)*Srows + i)*DH + d].  grid = (M/64, H).
// Destination selected in-kernel by widx (0:QI 1:KI 2:QP 3:KP 4:V).
// ---------------------------------------------------------------------------
__global__ void __launch_bounds__(256) k_gemm_proj(const float* __restrict__ A,
                                                   int widx,
                                                   int Srows) {
    float* dst = (widx == 0) ? g_QI : (widx == 1) ? g_KI
               : (widx == 2) ? g_QP : (widx == 3) ? g_KP : g_V;
    const float* W = g_Wp + (size_t)widx * D * D;
    __shared__ float As[16][68];   // [k][m]
    __shared__ float Bs[16][68];   // [k][n]
    const int m0 = blockIdx.x * 64;
    const int h  = blockIdx.y;
    const int t  = threadIdx.x;
    const int tx = t & 15, ty = t >> 4;
    const int lm = t >> 2, lkq = (t & 3) * 4;
    const int lk = t >> 4, lnq = (t & 15) * 4;
    float acc[4][4] = {};
    for (int k0 = 0; k0 < D; k0 += 16) {
        float4 va = *reinterpret_cast<const float4*>(&A[(size_t)(m0 + lm) * D + k0 + lkq]);
        As[lkq + 0][lm] = va.x; As[lkq + 1][lm] = va.y;
        As[lkq + 2][lm] = va.z; As[lkq + 3][lm] = va.w;
        *reinterpret_cast<float4*>(&Bs[lk][lnq]) =
            *reinterpret_cast<const float4*>(&W[(size_t)(k0 + lk) * D + h * DH + lnq]);
        __syncthreads();
#pragma unroll
        for (int k = 0; k < 16; ++k) {
            float4 a = *reinterpret_cast<const float4*>(&As[k][ty * 4]);
            float4 b = *reinterpret_cast<const float4*>(&Bs[k][tx * 4]);
            FMA16(acc, a, b)
        }
        __syncthreads();
    }
#pragma unroll
    for (int u = 0; u < 4; ++u) {
        int m = m0 + ty * 4 + u;
        int bb = m / Srows, i = m % Srows;
        float4 o = make_float4(acc[u][0], acc[u][1], acc[u][2], acc[u][3]);
        *reinterpret_cast<float4*>(
            &dst[(((size_t)bb * H + h) * Srows + i) * DH + tx * 4]) = o;
    }
}

// ---------------------------------------------------------------------------
// QK^T batched: S[g,i,j] = scale * sum_d Q[g,i,d]*K[g,j,d]
// grid = (S/64, S/64, G). stream=0: content (g_QI/g_KI -> g_SI, G=24)
//                          stream=1: positional (g_QP/g_KP -> g_SP, G=12)
// ---------------------------------------------------------------------------
__global__ void __launch_bounds__(256) k_gemm_qk(int stream) {
    const float* Q  = stream ? g_QP : g_QI;
    const float* Kp = stream ? g_KP : g_KI;
    float* Sout     = stream ? g_SP : g_SI;
    __shared__ float Qs[64][68];   // [d][i]
    __shared__ float Ks[64][68];   // [d][j]
    const int g  = blockIdx.z;
    const int i0 = blockIdx.x * 64, j0 = blockIdx.y * 64;
    const float* Qg = Q  + (size_t)g * S * DH;
    const float* Kg = Kp + (size_t)g * S * DH;
    const int t = threadIdx.x, tx = t & 15, ty = t >> 4;
#pragma unroll
    for (int r = 0; r < 4; ++r) {
        int idx = t + 256 * r;
        int row = idx >> 4;
        int dq  = (idx & 15) * 4;
        float4 q = *reinterpret_cast<const float4*>(&Qg[(size_t)(i0 + row) * DH + dq]);
        Qs[dq + 0][row] = q.x; Qs[dq + 1][row] = q.y;
        Qs[dq + 2][row] = q.z; Qs[dq + 3][row] = q.w;
        float4 k = *reinterpret_cast<const float4*>(&Kg[(size_t)(j0 + row) * DH + dq]);
        Ks[dq + 0][row] = k.x; Ks[dq + 1][row] = k.y;
        Ks[dq + 2][row] = k.z; Ks[dq + 3][row] = k.w;
    }
    __syncthreads();
    float acc[4][4] = {};
#pragma unroll
    for (int k = 0; k < 64; ++k) {
        float4 a = *reinterpret_cast<const float4*>(&Qs[k][ty * 4]);
        float4 b = *reinterpret_cast<const float4*>(&Ks[k][tx * 4]);
        FMA16(acc, a, b)
    }
#pragma unroll
    for (int u = 0; u < 4; ++u) {
        float4 o = make_float4(acc[u][0] * SCALE_SM, acc[u][1] * SCALE_SM,
                               acc[u][2] * SCALE_SM, acc[u][3] * SCALE_SM);
        *reinterpret_cast<float4*>(
            &Sout[((size_t)g * S + i0 + ty * 4 + u) * S + j0 + tx * 4]) = o;
    }
}

// ---------------------------------------------------------------------------
// Block reductions for softmax rows (256 threads = 8 warps).
// ---------------------------------------------------------------------------
__device__ __forceinline__ float block_reduce_max(float v, float* red) {
#pragma unroll
    for (int o = 16; o; o >>= 1) v = fmaxf(v, __shfl_xor_sync(~0u, v, o));
    int w = threadIdx.x >> 5;
    if ((threadIdx.x & 31) == 0) red[w] = v;
    __syncthreads();
    float m = red[0];
#pragma unroll
    for (int i = 1; i < 8; ++i) m = fmaxf(m, red[i]);
    return m;
}
__device__ __forceinline__ float block_reduce_sum(float v, float* red) {
#pragma unroll
    for (int o = 16; o; o >>= 1) v += __shfl_xor_sync(~0u, v, o);
    int w = threadIdx.x >> 5;
    if ((threadIdx.x & 31) == 0) red[w] = v;
    __syncthreads();
    float s = red[0];
#pragma unroll
    for (int i = 1; i < 8; ++i) s += red[i];
    return s;
}

// In-place softmax over rows of length S=2048 on g_SP. One block per row.
__global__ void __launch_bounds__(256) k_softmax() {
    __shared__ float redm[8];
    __shared__ float reds[8];
    float* X = g_SP;
    const size_t base = (size_t)blockIdx.x * S;
    const int t = threadIdx.x;
    float4 v0 = *reinterpret_cast<const float4*>(&X[base + t * 4]);
    float4 v1 = *reinterpret_cast<const float4*>(&X[base + 1024 + t * 4]);
    float m = fmaxf(fmaxf(fmaxf(v0.x, v0.y), fmaxf(v0.z, v0.w)),
                    fmaxf(fmaxf(v1.x, v1.y), fmaxf(v1.z, v1.w)));
    m = block_reduce_max(m, redm);
    v0.x = __expf(v0.x - m); v0.y = __expf(v0.y - m);
    v0.z = __expf(v0.z - m); v0.w = __expf(v0.w - m);
    v1.x = __expf(v1.x - m); v1.y = __expf(v1.y - m);
    v1.z = __expf(v1.z - m); v1.w = __expf(v1.w - m);
    float s = v0.x + v0.y + v0.z + v0.w + v1.x + v1.y + v1.z + v1.w;
    s = block_reduce_sum(s, reds);
    float inv = 1.0f / s;
    v0.x *= inv; v0.y *= inv; v0.z *= inv; v0.w *= inv;
    v1.x *= inv; v1.y *= inv; v1.z *= inv; v1.w *= inv;
    *reinterpret_cast<float4*>(&X[base + t * 4]) = v0;
    *reinterpret_cast<float4*>(&X[base + 1024 + t * 4]) = v1;
}

// ---------------------------------------------------------------------------
// Fused softmax(content row in g_SI) + 0.5/0.5 blend with positional prob
// row from g_SP, written back into g_SI. blockIdx.x = g*S + i, g = b*H + h.
// ---------------------------------------------------------------------------
__global__ void __launch_bounds__(256) k_softmax_blend() {
    __shared__ float redm[8];
    __shared__ float reds[8];
    const int r = blockIdx.x;
    const int g = r >> 11;          // /S
    const int i = r & 2047;
    const int h = g % H;
    float* row = g_SI + (size_t)r * S;
    const float* prow = g_SP + ((size_t)h * S + i) * S;
    const int t = threadIdx.x;
    float4 v0 = *reinterpret_cast<const float4*>(&row[t * 4]);
    float4 v1 = *reinterpret_cast<const float4*>(&row[1024 + t * 4]);
    float m = fmaxf(fmaxf(fmaxf(v0.x, v0.y), fmaxf(v0.z, v0.w)),
                    fmaxf(fmaxf(v1.x, v1.y), fmaxf(v1.z, v1.w)));
    m = block_reduce_max(m, redm);
    v0.x = __expf(v0.x - m); v0.y = __expf(v0.y - m);
    v0.z = __expf(v0.z - m); v0.w = __expf(v0.w - m);
    v1.x = __expf(v1.x - m); v1.y = __expf(v1.y - m);
    v1.z = __expf(v1.z - m); v1.w = __expf(v1.w - m);
    float s = v0.x + v0.y + v0.z + v0.w + v1.x + v1.y + v1.z + v1.w;
    s = block_reduce_sum(s, reds);
    float inv = 0.5f / s;           // fold 0.5 blend weight into normalization
    float4 p0 = *reinterpret_cast<const float4*>(&prow[t * 4]);
    float4 p1 = *reinterpret_cast<const float4*>(&prow[1024 + t * 4]);
    v0.x = v0.x * inv + 0.5f * p0.x; v0.y = v0.y * inv + 0.5f * p0.y;
    v0.z = v0.z * inv + 0.5f * p0.z; v0.w = v0.w * inv + 0.5f * p0.w;
    v1.x = v1.x * inv + 0.5f * p1.x; v1.y = v1.y * inv + 0.5f * p1.y;
    v1.z = v1.z * inv + 0.5f * p1.z; v1.w = v1.w * inv + 0.5f * p1.w;
    *reinterpret_cast<float4*>(&row[t * 4]) = v0;
    *reinterpret_cast<float4*>(&row[1024 + t * 4]) = v1;
}

// ---------------------------------------------------------------------------
// Pack attn_prob from g_SI to output layout [B,S,S,H] (H innermost) via smem
// transpose. grid = (S/128, B*S). Coalesced reads over j; 1536B contig writes.
// ---------------------------------------------------------------------------
__global__ void __launch_bounds__(256) k_pack(float* __restrict__ outp) {
    __shared__ float sm[12][129];
    const int bi = blockIdx.y;              // b*S + i
    const int b = bi >> 11, i = bi & 2047;
    const int j0 = blockIdx.x * 128;
    const int t = threadIdx.x;
#pragma unroll
    for (int r = 0; r < 6; ++r) {
        int idx = t + 256 * r;              // 0..1535
        int h = idx >> 7, j = idx & 127;
        sm[h][j] = g_SI[(((size_t)b * H + h) * S + i) * S + j0 + j];
    }
    __syncthreads();
    float* o = outp + ((size_t)bi * S + j0) * H;
#pragma unroll
    for (int r = 0; r < 6; ++r) {
        int idx = t + 256 * r;
        int j = idx / 12, h = idx - j * 12;
        o[idx] = sm[h][j];
    }
}

// ---------------------------------------------------------------------------
// PV batched GEMM: AO[b,i,h*64+d] = sum_j P[g,i,j] * V[g,j,d], g=b*H+h.
// grid = (S/64, G_I)
// ---------------------------------------------------------------------------
__global__ void __launch_bounds__(256) k_gemm_pv() {
    __shared__ float Ps[16][68];   // [j][i]
    __shared__ float Vs[16][68];   // [j][d]
    const int g  = blockIdx.y;
    const int i0 = blockIdx.x * 64;
    const int b = g / H, h = g % H;
    const int t = threadIdx.x, tx = t & 15, ty = t >> 4;
    const int lm = t >> 2, lkq = (t & 3) * 4;
    const int lk = t >> 4, lnq = (t & 15) * 4;
    const float* Pg = g_SI + (size_t)g * S * S;
    const float* Vg = g_V  + (size_t)g * S * DH;
    float acc[4][4] = {};
    for (int k0 = 0; k0 < S; k0 += 16) {
        float4 a = *reinterpret_cast<const float4*>(&Pg[(size_t)(i0 + lm) * S + k0 + lkq]);
        Ps[lkq + 0][lm] = a.x; Ps[lkq + 1][lm] = a.y;
        Ps[lkq + 2][lm] = a.z; Ps[lkq + 3][lm] = a.w;
        *reinterpret_cast<float4*>(&Vs[lk][lnq]) =
            *reinterpret_cast<const float4*>(&Vg[(size_t)(k0 + lk) * DH + lnq]);
        __syncthreads();
#pragma unroll
        for (int k = 0; k < 16; ++k) {
            float4 av = *reinterpret_cast<const float4*>(&Ps[k][ty * 4]);
            float4 bv = *reinterpret_cast<const float4*>(&Vs[k][tx * 4]);
            FMA16(acc, av, bv)
        }
        __syncthreads();
    }
#pragma unroll
    for (int u = 0; u < 4; ++u) {
        float4 o = make_float4(acc[u][0], acc[u][1], acc[u][2], acc[u][3]);
        *reinterpret_cast<float4*>(
            &g_AO[((size_t)b * S + i0 + ty * 4 + u) * D + h * DH + tx * 4]) = o;
    }
}

// ---------------------------------------------------------------------------
// Final projection: out = AO[N_TOK,768] @ Wo[768,768]. grid = (N_TOK/64, D/64)
// ---------------------------------------------------------------------------
__global__ void __launch_bounds__(256) k_gemm_out(const float* __restrict__ W,
                                                  float* __restrict__ C) {
    __shared__ float As[16][68];
    __shared__ float Bs[16][68];
    const int m0 = blockIdx.x * 64;
    const int n0 = blockIdx.y * 64;
    const int t = threadIdx.x, tx = t & 15, ty = t >> 4;
    const int lm = t >> 2, lkq = (t & 3) * 4;
    const int lk = t >> 4, lnq = (t & 15) * 4;
    float acc[4][4] = {};
    for (int k0 = 0; k0 < D; k0 += 16) {
        float4 va = *reinterpret_cast<const float4*>(&g_AO[(size_t)(m0 + lm) * D + k0 + lkq]);
        As[lkq + 0][lm] = va.x; As[lkq + 1][lm] = va.y;
        As[lkq + 2][lm] = va.z; As[lkq + 3][lm] = va.w;
        *reinterpret_cast<float4*>(&Bs[lk][lnq]) =
            *reinterpret_cast<const float4*>(&W[(size_t)(k0 + lk) * D + n0 + lnq]);
        __syncthreads();
#pragma unroll
        for (int k = 0; k < 16; ++k) {
            float4 a = *reinterpret_cast<const float4*>(&As[k][ty * 4]);
            float4 b = *reinterpret_cast<const float4*>(&Bs[k][tx * 4]);
            FMA16(acc, a, b)
        }
        __syncthreads();
    }
#pragma unroll
    for (int u = 0; u < 4; ++u) {
        float4 o = make_float4(acc[u][0], acc[u][1], acc[u][2], acc[u][3]);
        *reinterpret_cast<float4*>(&C[(size_t)(m0 + ty * 4 + u) * D + n0 + tx * 4]) = o;
    }
}

// ---------------------------------------------------------------------------
extern "C" void kernel_launch(void* const* d_in, const int* in_sizes, int n_in,
                              void* d_out, int out_size) {
    const float* inp  = (const float*)d_in[0];
    const float* pos  = (const float*)d_in[1];
    const float* Wq_i = (const float*)d_in[2];
    const float* Wk_i = (const float*)d_in[3];
    const float* Wq_p = (const float*)d_in[4];
    const float* Wk_p = (const float*)d_in[5];
    const float* Wv   = (const float*)d_in[6];
    const float* Wo   = (const float*)d_in[7];
    float* out = (float*)d_out;

    // All scratch lives in __device__ globals referenced directly by the
    // kernels — kernel_launch contains nothing but kernel launches.

    // 1) permute all 5 projection weights to head-contiguous layout
    const int pb = (D * D + 255) / 256;
    k_permW<<<dim3(pb, 1, 5), 256>>>(Wq_i, Wk_i, Wq_p, Wk_p, Wv);

    // 2) projections (widx: 0=QI 1=KI 2=QP 3=KP 4=V), per-head output layout
    k_gemm_proj<<<dim3(N_TOK / 64, H), 256>>>(inp, 0, S);   // Q content
    k_gemm_proj<<<dim3(N_TOK / 64, H), 256>>>(inp, 1, S);   // K content
    k_gemm_proj<<<dim3(N_TOK / 64, H), 256>>>(inp, 4, S);   // V
    k_gemm_proj<<<dim3(S / 64,     H), 256>>>(pos, 2, S);   // Q positional
    k_gemm_proj<<<dim3(S / 64,     H), 256>>>(pos, 3, S);   // K positional

    // 3) scores
    k_gemm_qk<<<dim3(S / 64, S / 64, G_I), 256>>>(0);       // content -> g_SI
    k_gemm_qk<<<dim3(S / 64, S / 64, G_P), 256>>>(1);       // positional -> g_SP

    // 4) softmaxes + blend (blend result stays in g_SI)
    k_softmax<<<G_P * S, 256>>>();
    k_softmax_blend<<<G_I * S, 256>>>();

    // 5) attn_prob output in [B,S,S,H] layout
    k_pack<<<dim3(S / 128, B * S), 256>>>(out + OUT_ATTN);

    // 6) PV and final projection -> attn_out
    k_gemm_pv<<<dim3(S / 64, G_I), 256>>>();
    k_gemm_out<<<dim3(N_TOK / 64, D / 64), 256>>>(Wo, out);
}

// round 9
// speedup vs baseline: 2.8934x; 2.8934x over previous
#include <cuda_runtime.h>
#include <cuda_bf16.h>
#include <cstdint>

// ---------------------------------------------------------------------------
// FullSelfAttention (content + positional blend) — mma.sync bf16-split version
//   B=2, S=2048, D=768, H=12, DH=64, gamma=0.5, scale=1/8
// All GEMMs on tensor cores via mma.sync.m16n8k16 (bf16, HMMA — plain sm_103
// target; tcgen05 unavailable in this build) with 3-product hi/lo splitting.
// Outputs: [0) attn_out [B,S,D]  [3145728) attn_prob [B,S,S,H]
// ---------------------------------------------------------------------------

static constexpr int B_ = 2, S = 2048, D = 768, H = 12, DH = 64;
static constexpr int NT = B_ * S;        // 4096 tokens
static constexpr int GI = B_ * H;        // 24 content heads
static constexpr int GP = H;             // 12 positional heads
static constexpr float SCL = 0.125f;
static constexpr size_t OUT_ATTN = (size_t)B_ * S * D;

typedef __nv_bfloat16 bf;

// --------------------------- device scratch --------------------------------
__device__ __align__(256) bf g_INH[(size_t)NT * D];
__device__ __align__(256) bf g_INL[(size_t)NT * D];
__device__ __align__(256) bf g_PEH[(size_t)S * D];
__device__ __align__(256) bf g_PEL[(size_t)S * D];
__device__ __align__(256) bf g_WTH[(size_t)6 * D * D];   // W^T (n-major) hi
__device__ __align__(256) bf g_WTL[(size_t)6 * D * D];   // W^T lo
__device__ __align__(256) bf g_QH [(size_t)GI * S * DH];
__device__ __align__(256) bf g_QL [(size_t)GI * S * DH];
__device__ __align__(256) bf g_KH [(size_t)GI * S * DH];
__device__ __align__(256) bf g_KL [(size_t)GI * S * DH];
__device__ __align__(256) bf g_QPH[(size_t)GP * S * DH];
__device__ __align__(256) bf g_QPL[(size_t)GP * S * DH];
__device__ __align__(256) bf g_KPH[(size_t)GP * S * DH];
__device__ __align__(256) bf g_KPL[(size_t)GP * S * DH];
__device__ __align__(256) bf g_VTH[(size_t)GI * DH * S]; // V transposed [g,d,j]
__device__ __align__(256) bf g_VTL[(size_t)GI * DH * S];
__device__ __align__(256) float g_SI[(size_t)GI * S * S];
__device__ __align__(256) float g_SP[(size_t)GP * S * S];
__device__ __align__(256) bf g_PRH[(size_t)GI * S * S];  // blended probs hi/lo
__device__ __align__(256) bf g_PRL[(size_t)GI * S * S];
__device__ __align__(256) bf g_AOH[(size_t)NT * D];
__device__ __align__(256) bf g_AOL[(size_t)NT * D];

// --------------------------- smem layout -----------------------------------
// padded row stride 72 bf16 (144 B) -> 16B-aligned rows, conflict-free ldmatrix
static constexpr uint32_t SA_H = 0;          // A hi: 128 x 72 bf16 = 18432 B
static constexpr uint32_t SA_L = 18432;      // A lo
static constexpr uint32_t SB_H = 36864;      // B hi: 64 x 72 bf16 = 9216 B
static constexpr uint32_t SB_L = 46080;      // B lo
static constexpr uint32_t SMEM_SZ = 55296;

// --------------------------- helpers ---------------------------------------
__device__ __forceinline__ uint32_t smem_u32(const void* p) {
    uint32_t a;
    asm("{ .reg .u64 t; cvta.to.shared.u64 t, %1; cvt.u32.u64 %0, t; }"
        : "=r"(a) : "l"(p));
    return a;
}
__device__ __forceinline__ void ldsm4(uint32_t* r, uint32_t addr) {
    asm volatile("ldmatrix.sync.aligned.m8n8.x4.shared.b16 {%0,%1,%2,%3}, [%4];"
                 : "=r"(r[0]), "=r"(r[1]), "=r"(r[2]), "=r"(r[3]) : "r"(addr));
}
__device__ __forceinline__ void hmma(float* d, const uint32_t* a, const uint32_t* b) {
    asm volatile(
        "mma.sync.aligned.m16n8k16.row.col.f32.bf16.bf16.f32 "
        "{%0,%1,%2,%3}, {%4,%5,%6,%7}, {%8,%9}, {%0,%1,%2,%3};"
        : "+f"(d[0]), "+f"(d[1]), "+f"(d[2]), "+f"(d[3])
        : "r"(a[0]), "r"(a[1]), "r"(a[2]), "r"(a[3]), "r"(b[0]), "r"(b[1]));
}
__device__ __forceinline__ void wr_pair_hl(bf* ph, bf* pl, size_t off,
                                           float x0, float x1) {
    bf h0 = __float2bfloat16(x0), h1 = __float2bfloat16(x1);
    bf l0 = __float2bfloat16(x0 - __bfloat162float(h0));
    bf l1 = __float2bfloat16(x1 - __bfloat162float(h1));
    *reinterpret_cast<__nv_bfloat162*>(ph + off) = __halves2bfloat162(h0, h1);
    *reinterpret_cast<__nv_bfloat162*>(pl + off) = __halves2bfloat162(l0, l1);
}

// ---------------------------------------------------------------------------
// Generic CTA-tile GEMM core: C[128 x 64] = (Ah+Al)[128 x K] @ (Bh+Bl)^T,
// B stored n-major [64][K]. 256 threads, 8 warps (4M x 2N), warp tile 32x32.
// acc[mt][nt][e]: mt in {0,1} (16-row tiles), nt in {0..3} (8-col tiles),
// e: {(r,c),(r,c+1),(r+8,c),(r+8,c+1)} with r=lid>>2, c=2*(lid&3).
// 3-product split: AhBh + AhBl + AlBh.
// ---------------------------------------------------------------------------
__device__ __forceinline__ void gemm_core(char* sm,
                                          const bf* __restrict__ Ah,
                                          const bf* __restrict__ Al, size_t ars,
                                          const bf* __restrict__ Bh,
                                          const bf* __restrict__ Bl, size_t brs,
                                          int nchunks, float acc[2][4][4]) {
    const uint32_t sb = smem_u32(sm);
    const int t = threadIdx.x, wid = t >> 5, lid = t & 31;
    const int warpM = wid >> 1, warpN = wid & 1;

    // ldmatrix lane-address offsets (bytes, relative to array base)
    const int arow = (lid & 7) + ((lid >> 3) & 1) * 8;
    const int acol = (lid >> 4) * 8;
    uint32_t roa[2];
#pragma unroll
    for (int mt = 0; mt < 2; ++mt)
        roa[mt] = (uint32_t)(((warpM * 32 + mt * 16 + arow) * 72 + acol) * 2);
    const int brow = (lid & 7) + ((lid >> 4) & 1) * 8;
    const int bcol = ((lid >> 3) & 1) * 8;
    uint32_t rob[2];
#pragma unroll
    for (int np = 0; np < 2; ++np)
        rob[np] = (uint32_t)(((warpN * 32 + np * 16 + brow) * 72 + bcol) * 2);

    for (int c = 0; c < nchunks; ++c) {
        const size_t ko = (size_t)c * 64;
        // stage A (128 x 64) hi/lo
#pragma unroll
        for (int u = t; u < 1024; u += 256) {
            int row = u >> 3, c8 = u & 7;
            uint32_t so = (uint32_t)(row * 144 + c8 * 16);
            *reinterpret_cast<uint4*>(sm + SA_H + so) =
                *reinterpret_cast<const uint4*>(Ah + (size_t)row * ars + ko + c8 * 8);
            *reinterpret_cast<uint4*>(sm + SA_L + so) =
                *reinterpret_cast<const uint4*>(Al + (size_t)row * ars + ko + c8 * 8);
        }
        // stage B (64 x 64) hi/lo
#pragma unroll
        for (int u = t; u < 512; u += 256) {
            int row = u >> 3, c8 = u & 7;
            uint32_t so = (uint32_t)(row * 144 + c8 * 16);
            *reinterpret_cast<uint4*>(sm + SB_H + so) =
                *reinterpret_cast<const uint4*>(Bh + (size_t)row * brs + ko + c8 * 8);
            *reinterpret_cast<uint4*>(sm + SB_L + so) =
                *reinterpret_cast<const uint4*>(Bl + (size_t)row * brs + ko + c8 * 8);
        }
        __syncthreads();
#pragma unroll
        for (int ks = 0; ks < 4; ++ks) {
            uint32_t ah[2][4], al[2][4], bh[2][4], bl[2][4];
#pragma unroll
            for (int mt = 0; mt < 2; ++mt) {
                ldsm4(ah[mt], sb + SA_H + roa[mt] + ks * 32);
                ldsm4(al[mt], sb + SA_L + roa[mt] + ks * 32);
            }
#pragma unroll
            for (int np = 0; np < 2; ++np) {
                ldsm4(bh[np], sb + SB_H + rob[np] + ks * 32);
                ldsm4(bl[np], sb + SB_L + rob[np] + ks * 32);
            }
#pragma unroll
            for (int mt = 0; mt < 2; ++mt)
#pragma unroll
                for (int nt = 0; nt < 4; ++nt) {
                    const uint32_t* bhp = &bh[nt >> 1][(nt & 1) * 2];
                    const uint32_t* blp = &bl[nt >> 1][(nt & 1) * 2];
                    hmma(acc[mt][nt], ah[mt], bhp);
                    hmma(acc[mt][nt], ah[mt], blp);
                    hmma(acc[mt][nt], al[mt], bhp);
                }
        }
        __syncthreads();
    }
}

// ---------------------------------------------------------------------------
// prep kernels
// ---------------------------------------------------------------------------
__global__ void __launch_bounds__(256) k_split(const float* __restrict__ src, int which) {
    size_t n = which ? (size_t)S * D : (size_t)NT * D;
    bf* dh = which ? g_PEH : g_INH;
    bf* dl = which ? g_PEL : g_INL;
    size_t i4 = ((size_t)blockIdx.x * 256 + threadIdx.x) * 4;
    if (i4 >= n) return;
    float4 v = *reinterpret_cast<const float4*>(src + i4);
    wr_pair_hl(dh, dl, i4, v.x, v.y);
    wr_pair_hl(dh, dl, i4 + 2, v.z, v.w);
}

// W^T[w][n][k]; w<5 head-permuted (orig col = (n%64)*H + n/64), w=5 Wo plain.
__global__ void __launch_bounds__(256) k_prepW(const float* __restrict__ W0,
                                               const float* __restrict__ W1,
                                               const float* __restrict__ W2,
                                               const float* __restrict__ W3,
                                               const float* __restrict__ W4,
                                               const float* __restrict__ W5) {
    int idx = blockIdx.x * 256 + threadIdx.x;
    if (idx >= D * D) return;
    int w = blockIdx.z;
    const float* Ws = (w == 0) ? W0 : (w == 1) ? W1 : (w == 2) ? W2
                    : (w == 3) ? W3 : (w == 4) ? W4 : W5;
    int n = idx / D, k = idx % D;
    int col = (w == 5) ? n : ((n & 63) * H + (n >> 6));
    float v = Ws[(size_t)k * D + col];
    bf hi = __float2bfloat16(v);
    g_WTH[(size_t)w * D * D + idx] = hi;
    g_WTL[(size_t)w * D * D + idx] = __float2bfloat16(v - __bfloat162float(hi));
}

// ---------------------------------------------------------------------------
// Projection: [128 tokens x 64 head-dims], K=768 (12 chunks). grid (M/128, H)
// widx: 0 Qc, 1 Kc, 2 Qp, 3 Kp, 4 V (epilogue transposes V to [g,d,j]).
// ---------------------------------------------------------------------------
__global__ void __launch_bounds__(256) k_mma_proj(int widx) {
    extern __shared__ char sm[];
    const int t = threadIdx.x, wid = t >> 5, lid = t & 31;
    const int warpM = wid >> 1, warpN = wid & 1;
    const int m0 = blockIdx.x * 128, h = blockIdx.y;
    const bool isPos = (widx == 2 || widx == 3);
    const bf* Ah = (isPos ? g_PEH : g_INH) + (size_t)m0 * D;
    const bf* Al = (isPos ? g_PEL : g_INL) + (size_t)m0 * D;
    const bf* Bh = g_WTH + ((size_t)widx * D + h * DH) * D;
    const bf* Bl = g_WTL + ((size_t)widx * D + h * DH) * D;
    float acc[2][4][4] = {};
    gemm_core(sm, Ah, Al, D, Bh, Bl, D, 12, acc);

    const int r0 = lid >> 2, c0 = (lid & 3) * 2;
    if (widx == 4) {
        float* smf = reinterpret_cast<float*>(sm);   // [128][65]
#pragma unroll
        for (int mt = 0; mt < 2; ++mt)
#pragma unroll
            for (int nt = 0; nt < 4; ++nt) {
                int rr = warpM * 32 + mt * 16 + r0;
                int cc = warpN * 32 + nt * 8 + c0;
                smf[rr * 65 + cc] = acc[mt][nt][0];
                smf[rr * 65 + cc + 1] = acc[mt][nt][1];
                smf[(rr + 8) * 65 + cc] = acc[mt][nt][2];
                smf[(rr + 8) * 65 + cc + 1] = acc[mt][nt][3];
            }
        __syncthreads();
        const int d = t >> 2, jq = t & 3;
        const int b = m0 >> 11, i0 = m0 & 2047;
        const int g = b * H + h;
        size_t vb = ((size_t)g * DH + d) * S + i0 + jq * 32;
#pragma unroll
        for (int jj = 0; jj < 32; jj += 2) {
            float x0 = smf[(jq * 32 + jj) * 65 + d];
            float x1 = smf[(jq * 32 + jj + 1) * 65 + d];
            wr_pair_hl(g_VTH, g_VTL, vb + jj, x0, x1);
        }
    } else {
        bf *dh, *dl;
        if (widx == 0)      { dh = g_QH;  dl = g_QL;  }
        else if (widx == 1) { dh = g_KH;  dl = g_KL;  }
        else if (widx == 2) { dh = g_QPH; dl = g_QPL; }
        else                { dh = g_KPH; dl = g_KPL; }
#pragma unroll
        for (int mt = 0; mt < 2; ++mt)
#pragma unroll
            for (int eh = 0; eh < 2; ++eh) {
                int m = m0 + warpM * 32 + mt * 16 + r0 + eh * 8;
                int g, i;
                if (isPos) { g = h; i = m; }
                else       { g = (m >> 11) * H + h; i = m & 2047; }
                size_t base = ((size_t)g * S + i) * DH;
#pragma unroll
                for (int nt = 0; nt < 4; ++nt)
                    wr_pair_hl(dh, dl, base + warpN * 32 + nt * 8 + c0,
                               acc[mt][nt][eh * 2], acc[mt][nt][eh * 2 + 1]);
            }
    }
}

// ---------------------------------------------------------------------------
// QK^T: scores[g, i0+128, j0+64], K=64 (1 chunk). grid (S/128, S/64, G)
// ---------------------------------------------------------------------------
__global__ void __launch_bounds__(256) k_mma_qk(int stream) {
    extern __shared__ char sm[];
    const int t = threadIdx.x, wid = t >> 5, lid = t & 31;
    const int warpM = wid >> 1, warpN = wid & 1;
    const int i0 = blockIdx.x * 128, j0 = blockIdx.y * 64, g = blockIdx.z;
    const bf* Ah = (stream ? g_QPH : g_QH) + ((size_t)g * S + i0) * DH;
    const bf* Al = (stream ? g_QPL : g_QL) + ((size_t)g * S + i0) * DH;
    const bf* Bh = (stream ? g_KPH : g_KH) + ((size_t)g * S + j0) * DH;
    const bf* Bl = (stream ? g_KPL : g_KL) + ((size_t)g * S + j0) * DH;
    float acc[2][4][4] = {};
    gemm_core(sm, Ah, Al, DH, Bh, Bl, DH, 1, acc);

    float* Sout = stream ? g_SP : g_SI;
    const int r0 = lid >> 2, c0 = (lid & 3) * 2;
#pragma unroll
    for (int mt = 0; mt < 2; ++mt)
#pragma unroll
        for (int eh = 0; eh < 2; ++eh) {
            size_t base = ((size_t)g * S + i0 + warpM * 32 + mt * 16 + r0 + eh * 8) * S
                          + j0 + warpN * 32 + c0;
#pragma unroll
            for (int nt = 0; nt < 4; ++nt) {
                float2 o = make_float2(acc[mt][nt][eh * 2] * SCL,
                                       acc[mt][nt][eh * 2 + 1] * SCL);
                *reinterpret_cast<float2*>(&Sout[base + nt * 8]) = o;
            }
        }
}

// ---------------------------------------------------------------------------
// PV: AO[b,i,h*64+d] = sum_j P[g,i,j] VT[g,d,j]; K=2048 (32 chunks).
// grid (S/128, GI)
// ---------------------------------------------------------------------------
__global__ void __launch_bounds__(256) k_mma_pv() {
    extern __shared__ char sm[];
    const int t = threadIdx.x, wid = t >> 5, lid = t & 31;
    const int warpM = wid >> 1, warpN = wid & 1;
    const int i0 = blockIdx.x * 128, g = blockIdx.y;
    const int b = g / H, h = g % H;
    const bf* Ah = g_PRH + ((size_t)g * S + i0) * S;
    const bf* Al = g_PRL + ((size_t)g * S + i0) * S;
    const bf* Bh = g_VTH + (size_t)g * DH * S;
    const bf* Bl = g_VTL + (size_t)g * DH * S;
    float acc[2][4][4] = {};
    gemm_core(sm, Ah, Al, S, Bh, Bl, S, 32, acc);

    const int r0 = lid >> 2, c0 = (lid & 3) * 2;
#pragma unroll
    for (int mt = 0; mt < 2; ++mt)
#pragma unroll
        for (int eh = 0; eh < 2; ++eh) {
            int i = i0 + warpM * 32 + mt * 16 + r0 + eh * 8;
            size_t base = ((size_t)b * S + i) * D + h * DH + warpN * 32 + c0;
#pragma unroll
            for (int nt = 0; nt < 4; ++nt)
                wr_pair_hl(g_AOH, g_AOL, base + nt * 8,
                           acc[mt][nt][eh * 2], acc[mt][nt][eh * 2 + 1]);
        }
}

// ---------------------------------------------------------------------------
// Out projection: out = AO @ Wo; K=768 (12 chunks). grid (NT/128, D/64)
// ---------------------------------------------------------------------------
__global__ void __launch_bounds__(256) k_mma_out(float* __restrict__ out) {
    extern __shared__ char sm[];
    const int t = threadIdx.x, wid = t >> 5, lid = t & 31;
    const int warpM = wid >> 1, warpN = wid & 1;
    const int m0 = blockIdx.x * 128, n0 = blockIdx.y * 64;
    const bf* Ah = g_AOH + (size_t)m0 * D;
    const bf* Al = g_AOL + (size_t)m0 * D;
    const bf* Bh = g_WTH + ((size_t)5 * D + n0) * D;
    const bf* Bl = g_WTL + ((size_t)5 * D + n0) * D;
    float acc[2][4][4] = {};
    gemm_core(sm, Ah, Al, D, Bh, Bl, D, 12, acc);

    const int r0 = lid >> 2, c0 = (lid & 3) * 2;
#pragma unroll
    for (int mt = 0; mt < 2; ++mt)
#pragma unroll
        for (int eh = 0; eh < 2; ++eh) {
            size_t base = (size_t)(m0 + warpM * 32 + mt * 16 + r0 + eh * 8) * D
                          + n0 + warpN * 32 + c0;
#pragma unroll
            for (int nt = 0; nt < 4; ++nt) {
                float2 o = make_float2(acc[mt][nt][eh * 2], acc[mt][nt][eh * 2 + 1]);
                *reinterpret_cast<float2*>(&out[base + nt * 8]) = o;
            }
        }
}

// ---------------------------------------------------------------------------
// Softmax machinery (256 threads = 8 warps per 2048-row)
// ---------------------------------------------------------------------------
__device__ __forceinline__ float brmax(float v, float* red) {
#pragma unroll
    for (int o = 16; o; o >>= 1) v = fmaxf(v, __shfl_xor_sync(~0u, v, o));
    if ((threadIdx.x & 31) == 0) red[threadIdx.x >> 5] = v;
    __syncthreads();
    float m = red[0];
#pragma unroll
    for (int i = 1; i < 8; ++i) m = fmaxf(m, red[i]);
    return m;
}
__device__ __forceinline__ float brsum(float v, float* red) {
#pragma unroll
    for (int o = 16; o; o >>= 1) v += __shfl_xor_sync(~0u, v, o);
    if ((threadIdx.x & 31) == 0) red[threadIdx.x >> 5] = v;
    __syncthreads();
    float s = red[0];
#pragma unroll
    for (int i = 1; i < 8; ++i) s += red[i];
    return s;
}

__global__ void __launch_bounds__(256) k_softmax() {
    __shared__ float redm[8], reds[8];
    const size_t base = (size_t)blockIdx.x * S;
    const int t = threadIdx.x;
    float4 v0 = *reinterpret_cast<const float4*>(&g_SP[base + t * 4]);
    float4 v1 = *reinterpret_cast<const float4*>(&g_SP[base + 1024 + t * 4]);
    float m = fmaxf(fmaxf(fmaxf(v0.x, v0.y), fmaxf(v0.z, v0.w)),
                    fmaxf(fmaxf(v1.x, v1.y), fmaxf(v1.z, v1.w)));
    m = brmax(m, redm);
    v0.x = __expf(v0.x - m); v0.y = __expf(v0.y - m);
    v0.z = __expf(v0.z - m); v0.w = __expf(v0.w - m);
    v1.x = __expf(v1.x - m); v1.y = __expf(v1.y - m);
    v1.z = __expf(v1.z - m); v1.w = __expf(v1.w - m);
    float s = v0.x + v0.y + v0.z + v0.w + v1.x + v1.y + v1.z + v1.w;
    s = brsum(s, reds);
    float inv = 1.0f / s;
    v0.x *= inv; v0.y *= inv; v0.z *= inv; v0.w *= inv;
    v1.x *= inv; v1.y *= inv; v1.z *= inv; v1.w *= inv;
    *reinterpret_cast<float4*>(&g_SP[base + t * 4]) = v0;
    *reinterpret_cast<float4*>(&g_SP[base + 1024 + t * 4]) = v1;
}

// softmax(content) + 0.5/0.5 blend with positional probs -> PRH/PRL (hi/lo)
__global__ void __launch_bounds__(256) k_softmax_blend() {
    __shared__ float redm[8], reds[8];
    const int r = blockIdx.x;
    const int g = r >> 11, i = r & 2047, h = g % H;
    const float* row = g_SI + (size_t)r * S;
    const float* prow = g_SP + ((size_t)h * S + i) * S;
    const int t = threadIdx.x;
    float4 v0 = *reinterpret_cast<const float4*>(&row[t * 4]);
    float4 v1 = *reinterpret_cast<const float4*>(&row[1024 + t * 4]);
    float m = fmaxf(fmaxf(fmaxf(v0.x, v0.y), fmaxf(v0.z, v0.w)),
                    fmaxf(fmaxf(v1.x, v1.y), fmaxf(v1.z, v1.w)));
    m = brmax(m, redm);
    v0.x = __expf(v0.x - m); v0.y = __expf(v0.y - m);
    v0.z = __expf(v0.z - m); v0.w = __expf(v0.w - m);
    v1.x = __expf(v1.x - m); v1.y = __expf(v1.y - m);
    v1.z = __expf(v1.z - m); v1.w = __expf(v1.w - m);
    float s = v0.x + v0.y + v0.z + v0.w + v1.x + v1.y + v1.z + v1.w;
    s = brsum(s, reds);
    float inv = 0.5f / s;
    float4 p0 = *reinterpret_cast<const float4*>(&prow[t * 4]);
    float4 p1 = *reinterpret_cast<const float4*>(&prow[1024 + t * 4]);
    v0.x = v0.x * inv + 0.5f * p0.x; v0.y = v0.y * inv + 0.5f * p0.y;
    v0.z = v0.z * inv + 0.5f * p0.z; v0.w = v0.w * inv + 0.5f * p0.w;
    v1.x = v1.x * inv + 0.5f * p1.x; v1.y = v1.y * inv + 0.5f * p1.y;
    v1.z = v1.z * inv + 0.5f * p1.z; v1.w = v1.w * inv + 0.5f * p1.w;
    size_t base = (size_t)r * S;
    wr_pair_hl(g_PRH, g_PRL, base + t * 4, v0.x, v0.y);
    wr_pair_hl(g_PRH, g_PRL, base + t * 4 + 2, v0.z, v0.w);
    wr_pair_hl(g_PRH, g_PRL, base + 1024 + t * 4, v1.x, v1.y);
    wr_pair_hl(g_PRH, g_PRL, base + 1024 + t * 4 + 2, v1.z, v1.w);
}

// attn_prob output: reconstruct fp32 probs, transpose to [B,S,S,H]
__global__ void __launch_bounds__(256) k_pack(float* __restrict__ outp) {
    __shared__ float smf[12][129];
    const int bi = blockIdx.y;
    const int b = bi >> 11, i = bi & 2047;
    const int j0 = blockIdx.x * 128;
    const int t = threadIdx.x;
#pragma unroll
    for (int r = 0; r < 6; ++r) {
        int idx = t + 256 * r;
        int h = idx >> 7, j = idx & 127;
        size_t src = (((size_t)b * H + h) * S + i) * S + j0 + j;
        smf[h][j] = __bfloat162float(g_PRH[src]) + __bfloat162float(g_PRL[src]);
    }
    __syncthreads();
    float* o = outp + ((size_t)bi * S + j0) * H;
#pragma unroll
    for (int r = 0; r < 6; ++r) {
        int idx = t + 256 * r;
        int j = idx / 12, h = idx - j * 12;
        o[idx] = smf[h][j];
    }
}

// ---------------------------------------------------------------------------
extern "C" void kernel_launch(void* const* d_in, const int* in_sizes, int n_in,
                              void* d_out, int out_size) {
    const float* inp  = (const float*)d_in[0];
    const float* pos  = (const float*)d_in[1];
    const float* Wq_i = (const float*)d_in[2];
    const float* Wk_i = (const float*)d_in[3];
    const float* Wq_p = (const float*)d_in[4];
    const float* Wk_p = (const float*)d_in[5];
    const float* Wv   = (const float*)d_in[6];
    const float* Wo   = (const float*)d_in[7];
    float* out = (float*)d_out;

    cudaFuncSetAttribute(k_mma_proj, cudaFuncAttributeMaxDynamicSharedMemorySize, SMEM_SZ);
    cudaFuncSetAttribute(k_mma_qk,   cudaFuncAttributeMaxDynamicSharedMemorySize, SMEM_SZ);
    cudaFuncSetAttribute(k_mma_pv,   cudaFuncAttributeMaxDynamicSharedMemorySize, SMEM_SZ);
    cudaFuncSetAttribute(k_mma_out,  cudaFuncAttributeMaxDynamicSharedMemorySize, SMEM_SZ);

    // prep: fp32 -> bf16 hi/lo
    k_split<<<(NT * D / 4 + 255) / 256, 256>>>(inp, 0);
    k_split<<<(S * D / 4 + 255) / 256, 256>>>(pos, 1);
    k_prepW<<<dim3((D * D + 255) / 256, 1, 6), 256>>>(Wq_i, Wk_i, Wq_p, Wk_p, Wv, Wo);

    // projections (0 Qc, 1 Kc, 4 V, 2 Qp, 3 Kp)
    k_mma_proj<<<dim3(NT / 128, H), 256, SMEM_SZ>>>(0);
    k_mma_proj<<<dim3(NT / 128, H), 256, SMEM_SZ>>>(1);
    k_mma_proj<<<dim3(NT / 128, H), 256, SMEM_SZ>>>(4);
    k_mma_proj<<<dim3(S / 128,  H), 256, SMEM_SZ>>>(2);
    k_mma_proj<<<dim3(S / 128,  H), 256, SMEM_SZ>>>(3);

    // scores
    k_mma_qk<<<dim3(S / 128, S / 64, GI), 256, SMEM_SZ>>>(0);
    k_mma_qk<<<dim3(S / 128, S / 64, GP), 256, SMEM_SZ>>>(1);

    // softmax + blend
    k_softmax<<<GP * S, 256>>>();
    k_softmax_blend<<<GI * S, 256>>>();

    // attn_prob output
    k_pack<<<dim3(S / 128, B_ * S), 256>>>(out + OUT_ATTN);

    // PV + out projection
    k_mma_pv<<<dim3(S / 128, GI), 256, SMEM_SZ>>>();
    k_mma_out<<<dim3(NT / 128, D / 64), 256, SMEM_SZ>>>(out);
}